// round 2
// baseline (speedup 1.0000x reference)
#include <cuda_runtime.h>

#define THREADS 512
#define LEAK 0.05f

// folded per-channel linear tail: Wfold[f][c] (f=0..31, c=0..63), bfold[c]
__device__ float g_Wfold[32 * 64];
__device__ float g_bfold[64];

// ---------------------------------------------------------------------------
// Prep: collapse the (purely linear) per-channel FC stack + detection head.
//   w_c[f]  = sum_{j,i} fw3[c][j] * fw2[c][j][i] * fw1[c][i][f]
//   bias_c  = fw3_c . (fw2_c . fb1_c + fb2_c) + fb3_c
//   g_c     = sum_j dw2[j] * dw1[j][c],   C = sum_j dw2[j]*db1[j] + db2
//   Wfold[f][c] = g_c * w_c[f],  bfold[c] = g_c * bias_c + C/64
// ---------------------------------------------------------------------------
__global__ void prep_kernel(const float* __restrict__ fw1, const float* __restrict__ fb1,
                            const float* __restrict__ fw2, const float* __restrict__ fb2,
                            const float* __restrict__ fw3, const float* __restrict__ fb3,
                            const float* __restrict__ dw1, const float* __restrict__ db1,
                            const float* __restrict__ dw2, const float* __restrict__ db2)
{
    int c = blockIdx.x;   // channel 0..63
    int t = threadIdx.x;  // 0..63
    __shared__ float u[64];   // u[i] = sum_j fw3[c][j]*fw2[c][j][i]
    __shared__ float t1[32];  // t1[j] = fw2[c][j].fb1[c] + fb2[c][j]

    float s = 0.f;
    #pragma unroll 4
    for (int j = 0; j < 32; j++)
        s += fw3[c * 32 + j] * fw2[(c * 32 + j) * 64 + t];
    u[t] = s;

    if (t < 32) {
        float a = fb2[c * 32 + t];
        #pragma unroll 4
        for (int i = 0; i < 64; i++)
            a += fw2[(c * 32 + t) * 64 + i] * fb1[c * 64 + i];
        t1[t] = a;
    }
    __syncthreads();

    float gc = 0.f;
    #pragma unroll 4
    for (int j = 0; j < 32; j++) gc += dw2[j] * dw1[j * 64 + c];

    if (t < 32) {
        float wv = 0.f;
        #pragma unroll 4
        for (int i = 0; i < 64; i++)
            wv += u[i] * fw1[(c * 64 + i) * 32 + t];
        g_Wfold[t * 64 + c] = gc * wv;
    }
    if (t == 0) {
        float bias = fb3[c];
        for (int j = 0; j < 32; j++) bias += fw3[c * 32 + j] * t1[j];
        float C = db2[0];
        for (int j = 0; j < 32; j++) C += dw2[j] * db1[j];
        g_bfold[c] = gc * bias + C * (1.0f / 64.0f);
    }
}

// ---------------------------------------------------------------------------
// Main: conv1(1->8,k3)+leaky+pool2, conv2(8->16,k3)+leaky+pool2 (pos 4 of
// conv2 is trimmed by the pool -> never computed), then folded 32-dot and a
// 64-channel reduction per sample.
// Thread layout: tid&63 = channel (x is channel-contiguous -> coalesced),
// tid>>6 = one of 8 samples per iteration; grid-stride over sample groups.
// Weights in shared, SoA [param][64] -> conflict-free per-lane LDS.
// Shared float layout:
//   sW1 [24][64] @0      sB1 [8][64] @1536   sW2 [384][64] @2048
//   sB2 [16][64] @26624  sWF [32][64] @27648 sBF [64] @29696
//   sRED[2][16] @29760 (parity double-buffer -> single barrier per iter)
// ---------------------------------------------------------------------------
#define SM_FLOATS 29792

__global__ __launch_bounds__(THREADS, 1)
void main_kernel(const float* __restrict__ x,
                 const float* __restrict__ w1, const float* __restrict__ b1,
                 const float* __restrict__ w2, const float* __restrict__ b2,
                 float* __restrict__ out, int B)
{
    extern __shared__ float sm[];
    float* sW1  = sm;
    float* sB1  = sm + 1536;
    float* sW2  = sm + 2048;
    float* sB2  = sm + 26624;
    float* sWF  = sm + 27648;
    float* sBF  = sm + 29696;
    float* sRED = sm + 29760;   // [2][16]

    const int tid = threadIdx.x;

    // stage weights (SoA transpose: global is [c][param], smem is [param][c])
    for (int i = tid; i < 1536; i += THREADS) {
        int p = i >> 6, c = i & 63;
        sW1[i] = w1[c * 24 + p];
    }
    for (int i = tid; i < 512; i += THREADS) {
        int p = i >> 6, c = i & 63;
        sB1[i] = b1[c * 8 + p];
    }
    for (int i = tid; i < 24576; i += THREADS) {
        int p = i >> 6, c = i & 63;
        int o = p / 48, k = (p / 16) % 3, oc = p % 16;
        sW2[i] = w2[((c * 16 + oc) * 8 + o) * 3 + k];
    }
    for (int i = tid; i < 1024; i += THREADS) {
        int p = i >> 6, c = i & 63;
        sB2[i] = b2[c * 16 + p];
    }
    for (int i = tid; i < 2048; i += THREADS) sWF[i] = g_Wfold[i];
    for (int i = tid; i < 64; i += THREADS) sBF[i] = g_bfold[i];
    __syncthreads();

    const int c = tid & 63;
    const int g = tid >> 6;   // sample-within-group 0..7
    const int w = tid >> 5;   // warp id 0..15
    const int NG = B >> 3;

    for (int grp = blockIdx.x; grp < NG; grp += gridDim.x) {
        const int s = (grp << 3) + g;
        const float* xp = x + (size_t)s * 1024 + c;
        float xr[16];
        #pragma unroll
        for (int t = 0; t < 16; t++) xr[t] = xp[t * 64];

        float acc[16][4];
        #pragma unroll
        for (int oc = 0; oc < 16; oc++) {
            float bb = sB2[oc * 64 + c];
            #pragma unroll
            for (int p = 0; p < 4; p++) acc[oc][p] = bb;
        }

        #pragma unroll
        for (int o = 0; o < 8; o++) {
            const float wa = sW1[(o * 3 + 0) * 64 + c];
            const float wb = sW1[(o * 3 + 1) * 64 + c];
            const float wc = sW1[(o * 3 + 2) * 64 + c];
            const float bb = sB1[o * 64 + c];
            float m[7];
            #pragma unroll
            for (int q = 0; q < 7; q++) {
                float h0 = fmaf(wa, xr[2 * q],     fmaf(wb, xr[2 * q + 1], fmaf(wc, xr[2 * q + 2], bb)));
                float h1 = fmaf(wa, xr[2 * q + 1], fmaf(wb, xr[2 * q + 2], fmaf(wc, xr[2 * q + 3], bb)));
                float M = fmaxf(h0, h1);           // leaky(max(a,b)) == max(leaky(a),leaky(b))
                m[q] = fmaxf(M, LEAK * M);
            }
            #pragma unroll
            for (int k = 0; k < 3; k++) {
                #pragma unroll
                for (int oc = 0; oc < 16; oc++) {
                    const float wv = sW2[((o * 3 + k) * 16 + oc) * 64 + c];
                    #pragma unroll
                    for (int p = 0; p < 4; p++)
                        acc[oc][p] = fmaf(wv, m[p + k], acc[oc][p]);
                }
            }
        }

        float r = sBF[c];
        #pragma unroll
        for (int oc = 0; oc < 16; oc++) {
            #pragma unroll
            for (int q = 0; q < 2; q++) {
                float M = fmaxf(acc[oc][2 * q], acc[oc][2 * q + 1]);
                float f = fmaxf(M, LEAK * M);
                r = fmaf(sWF[(oc * 2 + q) * 64 + c], f, r);
            }
        }

        // sum over 64 channels: 32-lane shfl, then pair the two warps per sample.
        // Parity double-buffer on sRED removes the trailing barrier.
        float* red = sRED + ((grp & 1) << 4);
        #pragma unroll
        for (int d = 16; d > 0; d >>= 1)
            r += __shfl_down_sync(0xffffffffu, r, d);
        if ((tid & 31) == 0) red[w] = r;
        __syncthreads();
        if (tid < 8) out[(grp << 3) + tid] = red[2 * tid] + red[2 * tid + 1];
    }
}

// ---------------------------------------------------------------------------
extern "C" void kernel_launch(void* const* d_in, const int* in_sizes, int n_in,
                              void* d_out, int out_size)
{
    const float* x   = (const float*)d_in[0];
    const float* w1  = (const float*)d_in[1];
    const float* b1  = (const float*)d_in[2];
    const float* w2  = (const float*)d_in[3];
    const float* b2  = (const float*)d_in[4];
    const float* fw1 = (const float*)d_in[5];
    const float* fb1 = (const float*)d_in[6];
    const float* fw2 = (const float*)d_in[7];
    const float* fb2 = (const float*)d_in[8];
    const float* fw3 = (const float*)d_in[9];
    const float* fb3 = (const float*)d_in[10];
    const float* dw1 = (const float*)d_in[11];
    const float* db1 = (const float*)d_in[12];
    const float* dw2 = (const float*)d_in[13];
    const float* db2 = (const float*)d_in[14];

    const int B = in_sizes[0] / 1024;  // x is [B,1,16,8,8] = B*1024 floats
    const size_t smem = SM_FLOATS * sizeof(float);

    prep_kernel<<<64, 64>>>(fw1, fb1, fw2, fb2, fw3, fb3, dw1, db1, dw2, db2);

    cudaFuncSetAttribute(main_kernel, cudaFuncAttributeMaxDynamicSharedMemorySize, (int)smem);
    main_kernel<<<148, THREADS, smem>>>(x, w1, b1, w2, b2, (float*)d_out, B);
}

// round 3
// speedup vs baseline: 1.1586x; 1.1586x over previous
#include <cuda_runtime.h>

#define THREADS 512
#define LEAK 0.05f

// folded per-channel linear tail: Wfold[f][c] (f=0..31, c=0..63), bfold[c]
__device__ float g_Wfold[32 * 64];
__device__ float g_bfold[64];

// ---------------------------------------------------------------------------
// packed f32x2 helpers
// ---------------------------------------------------------------------------
__device__ __forceinline__ unsigned long long pack2(float lo, float hi) {
    unsigned long long d;
    asm("mov.b64 %0, {%1, %2};" : "=l"(d) : "f"(lo), "f"(hi));
    return d;
}
__device__ __forceinline__ unsigned long long dup2(float v) {
    unsigned long long d;
    asm("mov.b64 %0, {%1, %1};" : "=l"(d) : "f"(v));
    return d;
}
__device__ __forceinline__ void ffma2(unsigned long long& acc,
                                      unsigned long long a, unsigned long long b) {
    asm("fma.rn.f32x2 %0, %1, %2, %0;" : "+l"(acc) : "l"(a), "l"(b));
}
__device__ __forceinline__ void unpack2(float& lo, float& hi, unsigned long long v) {
    asm("mov.b64 {%0, %1}, %2;" : "=f"(lo), "=f"(hi) : "l"(v));
}

// ---------------------------------------------------------------------------
// Prep: collapse the (purely linear) per-channel FC stack + detection head.
// ---------------------------------------------------------------------------
__global__ void prep_kernel(const float* __restrict__ fw1, const float* __restrict__ fb1,
                            const float* __restrict__ fw2, const float* __restrict__ fb2,
                            const float* __restrict__ fw3, const float* __restrict__ fb3,
                            const float* __restrict__ dw1, const float* __restrict__ db1,
                            const float* __restrict__ dw2, const float* __restrict__ db2)
{
    int c = blockIdx.x;   // channel 0..63
    int t = threadIdx.x;  // 0..63
    __shared__ float u[64];   // u[i] = sum_j fw3[c][j]*fw2[c][j][i]
    __shared__ float t1[32];  // t1[j] = fw2[c][j].fb1[c] + fb2[c][j]

    float s = 0.f;
    #pragma unroll 4
    for (int j = 0; j < 32; j++)
        s += fw3[c * 32 + j] * fw2[(c * 32 + j) * 64 + t];
    u[t] = s;

    if (t < 32) {
        float a = fb2[c * 32 + t];
        #pragma unroll 4
        for (int i = 0; i < 64; i++)
            a += fw2[(c * 32 + t) * 64 + i] * fb1[c * 64 + i];
        t1[t] = a;
    }
    __syncthreads();

    float gc = 0.f;
    #pragma unroll 4
    for (int j = 0; j < 32; j++) gc += dw2[j] * dw1[j * 64 + c];

    if (t < 32) {
        float wv = 0.f;
        #pragma unroll 4
        for (int i = 0; i < 64; i++)
            wv += u[i] * fw1[(c * 64 + i) * 32 + t];
        g_Wfold[t * 64 + c] = gc * wv;
    }
    if (t == 0) {
        float bias = fb3[c];
        for (int j = 0; j < 32; j++) bias += fw3[c * 32 + j] * t1[j];
        float C = db2[0];
        for (int j = 0; j < 32; j++) C += dw2[j] * db1[j];
        g_bfold[c] = gc * bias + C * (1.0f / 64.0f);
    }
}

// ---------------------------------------------------------------------------
// Main kernel.
// Thread layout: tid&63 = channel c (x channel-contiguous -> coalesced LDG),
// tid>>6 = one of 8 samples/iter; grid-stride over sample groups.
//
// Shared float layout (all lane-major, vector-width innermost => conflict-free
// LDS.64/LDS.128 in half/quarter-warp phases):
//   sW1q [8 o][64 c][4:(wa,wb,wc,b1)]          @0      (2048)
//   sW2q [96:(o,k,ocq)][64 c][4:oc%4]          @2048   (24576)
//   sB2q [4 ocq][64 c][4]                      @26624  (1024)
//   sWFq [16 oc][64 c][2:poolpos]              @27648  (2048)
//   sBF  [64]                                  @29696
//   sRED [2][16] parity double-buffer          @29760
// ---------------------------------------------------------------------------
#define SM_FLOATS 29792

__global__ __launch_bounds__(THREADS, 1)
void main_kernel(const float* __restrict__ x,
                 const float* __restrict__ w1, const float* __restrict__ b1,
                 const float* __restrict__ w2, const float* __restrict__ b2,
                 float* __restrict__ out, int B)
{
    extern __shared__ float sm[];
    float* sW1q = sm;
    float* sW2q = sm + 2048;
    float* sB2q = sm + 26624;
    float* sWFq = sm + 27648;
    float* sBF  = sm + 29696;
    float* sRED = sm + 29760;

    const int tid = threadIdx.x;

    // ---- stage weights (SoA transpose; one-time, coalesced smem stores) ----
    for (int i = tid; i < 2048; i += THREADS) {           // sW1q
        int o = i >> 8, c = (i >> 2) & 63, j = i & 3;
        sW1q[i] = (j < 3) ? w1[c * 24 + o * 3 + j] : b1[c * 8 + o];
    }
    for (int i = tid; i < 24576; i += THREADS) {          // sW2q
        int row = i >> 8, c = (i >> 2) & 63, j = i & 3;
        int o = row / 12, k = (row / 4) % 3, ocq = row & 3;
        int oc = ocq * 4 + j;
        sW2q[i] = w2[((c * 16 + oc) * 8 + o) * 3 + k];
    }
    for (int i = tid; i < 1024; i += THREADS) {           // sB2q
        int ocq = i >> 8, c = (i >> 2) & 63, j = i & 3;
        sB2q[i] = b2[c * 16 + ocq * 4 + j];
    }
    for (int i = tid; i < 2048; i += THREADS) {           // sWFq
        int oc = i >> 7, c = (i >> 1) & 63, q = i & 1;
        sWFq[i] = g_Wfold[(oc * 2 + q) * 64 + c];
    }
    for (int i = tid; i < 64; i += THREADS) sBF[i] = g_bfold[i];
    __syncthreads();

    const int c = tid & 63;
    const int g = tid >> 6;   // sample-within-group 0..7
    const int w = tid >> 5;   // warp id 0..15
    const int NG = B >> 3;

    for (int grp = blockIdx.x; grp < NG; grp += gridDim.x) {
        const int s = (grp << 3) + g;
        const float* xp = x + (size_t)s * 1024 + c;
        // only x[0..13] are live: m[6] feeds conv2 position 4, which the pool trims
        float xr[14];
        #pragma unroll
        for (int t = 0; t < 14; t++) xr[t] = xp[t * 64];

        // acc[ocq][pair][pos]: pair 0 = (oc=4q+0, 4q+1), pair 1 = (4q+2, 4q+3)
        unsigned long long acc[4][2][4];
        #pragma unroll
        for (int ocq = 0; ocq < 4; ocq++) {
            ulonglong2 bv = *reinterpret_cast<const ulonglong2*>(&sB2q[(ocq << 8) + (c << 2)]);
            #pragma unroll
            for (int p = 0; p < 4; p++) { acc[ocq][0][p] = bv.x; acc[ocq][1][p] = bv.y; }
        }

        #pragma unroll
        for (int o = 0; o < 8; o++) {
            const float4 wv1 = *reinterpret_cast<const float4*>(&sW1q[(o << 8) + (c << 2)]);
            unsigned long long md[6];
            #pragma unroll
            for (int q = 0; q < 6; q++) {
                float h0 = fmaf(wv1.x, xr[2 * q],     fmaf(wv1.y, xr[2 * q + 1], fmaf(wv1.z, xr[2 * q + 2], wv1.w)));
                float h1 = fmaf(wv1.x, xr[2 * q + 1], fmaf(wv1.y, xr[2 * q + 2], fmaf(wv1.z, xr[2 * q + 3], wv1.w)));
                float M = fmaxf(h0, h1);            // leaky(max(a,b)) == max(leaky(a),leaky(b))
                md[q] = dup2(fmaxf(M, LEAK * M));
            }
            #pragma unroll
            for (int k = 0; k < 3; k++) {
                #pragma unroll
                for (int ocq = 0; ocq < 4; ocq++) {
                    ulonglong2 wv = *reinterpret_cast<const ulonglong2*>(
                        &sW2q[(((o * 3 + k) << 2) + ocq) * 256 + (c << 2)]);
                    #pragma unroll
                    for (int p = 0; p < 4; p++) {
                        ffma2(acc[ocq][0][p], wv.x, md[p + k]);
                        ffma2(acc[ocq][1][p], wv.y, md[p + k]);
                    }
                }
            }
        }

        // epilogue: pool+leaky on conv2, then folded 32-dot (packed pairs)
        unsigned long long r2 = pack2(sBF[c], 0.0f);
        #pragma unroll
        for (int ocq = 0; ocq < 4; ocq++) {
            #pragma unroll
            for (int h = 0; h < 2; h++) {
                float lo[4], hi[4];
                #pragma unroll
                for (int p = 0; p < 4; p++) unpack2(lo[p], hi[p], acc[ocq][h][p]);
                const int oc0 = ocq * 4 + h * 2;      // lo lane -> oc0, hi lane -> oc0+1
                {
                    float M0 = fmaxf(lo[0], lo[1]), M1 = fmaxf(lo[2], lo[3]);
                    float f0 = fmaxf(M0, LEAK * M0), f1 = fmaxf(M1, LEAK * M1);
                    unsigned long long wf = *reinterpret_cast<const unsigned long long*>(
                        &sWFq[(oc0 << 7) + (c << 1)]);
                    ffma2(r2, wf, pack2(f0, f1));
                }
                {
                    float M0 = fmaxf(hi[0], hi[1]), M1 = fmaxf(hi[2], hi[3]);
                    float f0 = fmaxf(M0, LEAK * M0), f1 = fmaxf(M1, LEAK * M1);
                    unsigned long long wf = *reinterpret_cast<const unsigned long long*>(
                        &sWFq[((oc0 + 1) << 7) + (c << 1)]);
                    ffma2(r2, wf, pack2(f0, f1));
                }
            }
        }
        float rl, rh;
        unpack2(rl, rh, r2);
        float r = rl + rh;

        // sum over 64 channels: 32-lane shfl, then pair the two warps per sample.
        float* red = sRED + ((grp & 1) << 4);
        #pragma unroll
        for (int d = 16; d > 0; d >>= 1)
            r += __shfl_down_sync(0xffffffffu, r, d);
        if ((tid & 31) == 0) red[w] = r;
        __syncthreads();
        if (tid < 8) out[(grp << 3) + tid] = red[2 * tid] + red[2 * tid + 1];
    }
}

// ---------------------------------------------------------------------------
extern "C" void kernel_launch(void* const* d_in, const int* in_sizes, int n_in,
                              void* d_out, int out_size)
{
    const float* x   = (const float*)d_in[0];
    const float* w1  = (const float*)d_in[1];
    const float* b1  = (const float*)d_in[2];
    const float* w2  = (const float*)d_in[3];
    const float* b2  = (const float*)d_in[4];
    const float* fw1 = (const float*)d_in[5];
    const float* fb1 = (const float*)d_in[6];
    const float* fw2 = (const float*)d_in[7];
    const float* fb2 = (const float*)d_in[8];
    const float* fw3 = (const float*)d_in[9];
    const float* fb3 = (const float*)d_in[10];
    const float* dw1 = (const float*)d_in[11];
    const float* db1 = (const float*)d_in[12];
    const float* dw2 = (const float*)d_in[13];
    const float* db2 = (const float*)d_in[14];

    const int B = in_sizes[0] / 1024;  // x is [B,1,16,8,8] = B*1024 floats
    const size_t smem = SM_FLOATS * sizeof(float);

    prep_kernel<<<64, 64>>>(fw1, fb1, fw2, fb2, fw3, fb3, dw1, db1, dw2, db2);

    cudaFuncSetAttribute(main_kernel, cudaFuncAttributeMaxDynamicSharedMemorySize, (int)smem);
    main_kernel<<<148, THREADS, smem>>>(x, w1, b1, w2, b2, (float*)d_out, B);
}

// round 4
// speedup vs baseline: 1.1723x; 1.0118x over previous
#include <cuda_runtime.h>

#define THREADS 256
#define LEAK 0.05f

// folded per-channel linear tail: Wfold[f][c] (f=0..31, c=0..63), bfold[c]
__device__ float g_Wfold[32 * 64];
__device__ float g_bfold[64];

// ---------------------------------------------------------------------------
// packed f32x2 helpers
// ---------------------------------------------------------------------------
__device__ __forceinline__ unsigned long long pack2(float lo, float hi) {
    unsigned long long d;
    asm("mov.b64 %0, {%1, %2};" : "=l"(d) : "f"(lo), "f"(hi));
    return d;
}
__device__ __forceinline__ unsigned long long dup2(float v) {
    unsigned long long d;
    asm("mov.b64 %0, {%1, %1};" : "=l"(d) : "f"(v));
    return d;
}
__device__ __forceinline__ void ffma2(unsigned long long& acc,
                                      unsigned long long a, unsigned long long b) {
    asm("fma.rn.f32x2 %0, %1, %2, %0;" : "+l"(acc) : "l"(a), "l"(b));
}
__device__ __forceinline__ unsigned long long ffma2_3(unsigned long long a,
                                                      unsigned long long b,
                                                      unsigned long long c) {
    unsigned long long d;
    asm("fma.rn.f32x2 %0, %1, %2, %3;" : "=l"(d) : "l"(a), "l"(b), "l"(c));
    return d;
}
__device__ __forceinline__ void unpack2(float& lo, float& hi, unsigned long long v) {
    asm("mov.b64 {%0, %1}, %2;" : "=f"(lo), "=f"(hi) : "l"(v));
}

// ---------------------------------------------------------------------------
// Prep: collapse the (purely linear) per-channel FC stack + detection head.
// ---------------------------------------------------------------------------
__global__ void prep_kernel(const float* __restrict__ fw1, const float* __restrict__ fb1,
                            const float* __restrict__ fw2, const float* __restrict__ fb2,
                            const float* __restrict__ fw3, const float* __restrict__ fb3,
                            const float* __restrict__ dw1, const float* __restrict__ db1,
                            const float* __restrict__ dw2, const float* __restrict__ db2)
{
    int c = blockIdx.x;   // channel 0..63
    int t = threadIdx.x;  // 0..63
    __shared__ float u[64];   // u[i] = sum_j fw3[c][j]*fw2[c][j][i]
    __shared__ float t1[32];  // t1[j] = fw2[c][j].fb1[c] + fb2[c][j]

    float s = 0.f;
    #pragma unroll 4
    for (int j = 0; j < 32; j++)
        s += fw3[c * 32 + j] * fw2[(c * 32 + j) * 64 + t];
    u[t] = s;

    if (t < 32) {
        float a = fb2[c * 32 + t];
        #pragma unroll 4
        for (int i = 0; i < 64; i++)
            a += fw2[(c * 32 + t) * 64 + i] * fb1[c * 64 + i];
        t1[t] = a;
    }
    __syncthreads();

    float gc = 0.f;
    #pragma unroll 4
    for (int j = 0; j < 32; j++) gc += dw2[j] * dw1[j * 64 + c];

    if (t < 32) {
        float wv = 0.f;
        #pragma unroll 4
        for (int i = 0; i < 64; i++)
            wv += u[i] * fw1[(c * 64 + i) * 32 + t];
        g_Wfold[t * 64 + c] = gc * wv;
    }
    if (t == 0) {
        float bias = fb3[c];
        for (int j = 0; j < 32; j++) bias += fw3[c * 32 + j] * t1[j];
        float C = db2[0];
        for (int j = 0; j < 32; j++) C += dw2[j] * db1[j];
        g_bfold[c] = gc * bias + C * (1.0f / 64.0f);
    }
}

// ---------------------------------------------------------------------------
// Main kernel: 256 threads, each thread handles TWO samples (s, s+4) of one
// channel. Every shared-memory weight load is reused by both samples (LDS
// traffic halved per sample) and the 64 packed accumulators give enough ILP
// to cover LDS/LDG latency at 8 warps/SM.
//
// tid&63 = channel c; g = tid>>6 in 0..3; samples = grp*8 + g and grp*8 + g+4.
// conv1 is computed f32x2-packed across the sample pair; conv2 accumulators
// are f32x2-packed across oc-pairs (per sample), so weight ulonglong2 loads
// feed both samples with no duplication.
//
// Shared float layout (unchanged from R2):
//   sW1q [8 o][64 c][4:(wa,wb,wc,b1)]          @0      (2048)
//   sW2q [96:(o,k,ocq)][64 c][4:oc%4]          @2048   (24576)
//   sB2q [4 ocq][64 c][4]                      @26624  (1024)
//   sWFq [16 oc][64 c][2:poolpos]              @27648  (2048)
//   sBF  [64]                                  @29696
//   sRED [2 buf][8 warps][2 samples]           @29760  (32)
// ---------------------------------------------------------------------------
#define SM_FLOATS 29792

__global__ __launch_bounds__(THREADS, 1)
void main_kernel(const float* __restrict__ x,
                 const float* __restrict__ w1, const float* __restrict__ b1,
                 const float* __restrict__ w2, const float* __restrict__ b2,
                 float* __restrict__ out, int B)
{
    extern __shared__ float sm[];
    float* sW1q = sm;
    float* sW2q = sm + 2048;
    float* sB2q = sm + 26624;
    float* sWFq = sm + 27648;
    float* sBF  = sm + 29696;
    float* sRED = sm + 29760;

    const int tid = threadIdx.x;

    // ---- stage weights (SoA transpose; one-time) ----
    for (int i = tid; i < 2048; i += THREADS) {           // sW1q
        int o = i >> 8, c = (i >> 2) & 63, j = i & 3;
        sW1q[i] = (j < 3) ? w1[c * 24 + o * 3 + j] : b1[c * 8 + o];
    }
    for (int i = tid; i < 24576; i += THREADS) {          // sW2q
        int row = i >> 8, c = (i >> 2) & 63, j = i & 3;
        int o = row / 12, k = (row / 4) % 3, ocq = row & 3;
        int oc = ocq * 4 + j;
        sW2q[i] = w2[((c * 16 + oc) * 8 + o) * 3 + k];
    }
    for (int i = tid; i < 1024; i += THREADS) {           // sB2q
        int ocq = i >> 8, c = (i >> 2) & 63, j = i & 3;
        sB2q[i] = b2[c * 16 + ocq * 4 + j];
    }
    for (int i = tid; i < 2048; i += THREADS) {           // sWFq
        int oc = i >> 7, c = (i >> 1) & 63, q = i & 1;
        sWFq[i] = g_Wfold[(oc * 2 + q) * 64 + c];
    }
    for (int i = tid; i < 64; i += THREADS) sBF[i] = g_bfold[i];
    __syncthreads();

    const int c = tid & 63;
    const int g = tid >> 6;   // 0..3
    const int w = tid >> 5;   // warp id 0..7
    const int NG = B >> 3;    // 8 samples per group iter (4 g-slots x 2)

    for (int grp = blockIdx.x; grp < NG; grp += gridDim.x) {
        const float* xp0 = x + (size_t)(grp * 8 + g) * 1024 + c;
        const float* xp1 = xp0 + 4 * 1024;

        // xr packed across the sample pair; positions 14,15 are dead
        // (m[6] feeds only conv2 position 4, trimmed by the pool).
        unsigned long long xr[14];
        #pragma unroll
        for (int t = 0; t < 14; t++) xr[t] = pack2(xp0[t * 64], xp1[t * 64]);

        // acc[s][ocq][pair][pos]; pair lanes = (oc=4q+0,4q+1)/(4q+2,4q+3)
        unsigned long long acc[2][4][2][4];
        #pragma unroll
        for (int ocq = 0; ocq < 4; ocq++) {
            ulonglong2 bv = *reinterpret_cast<const ulonglong2*>(&sB2q[(ocq << 8) + (c << 2)]);
            #pragma unroll
            for (int p = 0; p < 4; p++) {
                acc[0][ocq][0][p] = bv.x; acc[0][ocq][1][p] = bv.y;
                acc[1][ocq][0][p] = bv.x; acc[1][ocq][1][p] = bv.y;
            }
        }

        #pragma unroll
        for (int o = 0; o < 8; o++) {
            const float4 wv1 = *reinterpret_cast<const float4*>(&sW1q[(o << 8) + (c << 2)]);
            const unsigned long long wa2 = dup2(wv1.x);
            const unsigned long long wb2 = dup2(wv1.y);
            const unsigned long long wc2 = dup2(wv1.z);
            const unsigned long long bb2 = dup2(wv1.w);

            // conv1 packed over sample pair, then scalar pool+leaky per sample
            unsigned long long md[2][6];
            #pragma unroll
            for (int q = 0; q < 6; q++) {
                unsigned long long h0 = ffma2_3(wa2, xr[2 * q],
                                        ffma2_3(wb2, xr[2 * q + 1],
                                        ffma2_3(wc2, xr[2 * q + 2], bb2)));
                unsigned long long h1 = ffma2_3(wa2, xr[2 * q + 1],
                                        ffma2_3(wb2, xr[2 * q + 2],
                                        ffma2_3(wc2, xr[2 * q + 3], bb2)));
                float a0, a1, b0, b1;
                unpack2(a0, a1, h0);
                unpack2(b0, b1, h1);
                float M0 = fmaxf(a0, b0), M1 = fmaxf(a1, b1);
                md[0][q] = dup2(fmaxf(M0, LEAK * M0));   // leaky(max)=max(leaky)
                md[1][q] = dup2(fmaxf(M1, LEAK * M1));
            }

            #pragma unroll
            for (int k = 0; k < 3; k++) {
                #pragma unroll
                for (int ocq = 0; ocq < 4; ocq++) {
                    ulonglong2 wv = *reinterpret_cast<const ulonglong2*>(
                        &sW2q[(((o * 3 + k) << 2) + ocq) * 256 + (c << 2)]);
                    #pragma unroll
                    for (int p = 0; p < 4; p++) {
                        ffma2(acc[0][ocq][0][p], wv.x, md[0][p + k]);
                        ffma2(acc[0][ocq][1][p], wv.y, md[0][p + k]);
                        ffma2(acc[1][ocq][0][p], wv.x, md[1][p + k]);
                        ffma2(acc[1][ocq][1][p], wv.y, md[1][p + k]);
                    }
                }
            }
        }

        // epilogue per sample: pool+leaky on conv2, folded 32-dot (oc-paired)
        float rs[2];
        #pragma unroll
        for (int s = 0; s < 2; s++) {
            unsigned long long r2 = pack2(sBF[c], 0.0f);
            #pragma unroll
            for (int ocq = 0; ocq < 4; ocq++) {
                #pragma unroll
                for (int h = 0; h < 2; h++) {
                    float lo[4], hi[4];
                    #pragma unroll
                    for (int p = 0; p < 4; p++) unpack2(lo[p], hi[p], acc[s][ocq][h][p]);
                    const int oc0 = ocq * 4 + h * 2;
                    {
                        float M0 = fmaxf(lo[0], lo[1]), M1 = fmaxf(lo[2], lo[3]);
                        float f0 = fmaxf(M0, LEAK * M0), f1 = fmaxf(M1, LEAK * M1);
                        unsigned long long wf = *reinterpret_cast<const unsigned long long*>(
                            &sWFq[(oc0 << 7) + (c << 1)]);
                        ffma2(r2, wf, pack2(f0, f1));
                    }
                    {
                        float M0 = fmaxf(hi[0], hi[1]), M1 = fmaxf(hi[2], hi[3]);
                        float f0 = fmaxf(M0, LEAK * M0), f1 = fmaxf(M1, LEAK * M1);
                        unsigned long long wf = *reinterpret_cast<const unsigned long long*>(
                            &sWFq[((oc0 + 1) << 7) + (c << 1)]);
                        ffma2(r2, wf, pack2(f0, f1));
                    }
                }
            }
            float rl, rh;
            unpack2(rl, rh, r2);
            rs[s] = rl + rh;
        }

        // 64-channel reduction: packed shfl over 32 lanes, then warp-pairing.
        unsigned long long rp = pack2(rs[0], rs[1]);
        #pragma unroll
        for (int d = 16; d > 0; d >>= 1) {
            unsigned long long o2 = __shfl_down_sync(0xffffffffu, rp, d);
            asm("add.rn.f32x2 %0, %0, %1;" : "+l"(rp) : "l"(o2));
        }
        float* red = sRED + ((grp & 1) << 4);
        if ((tid & 31) == 0) *reinterpret_cast<unsigned long long*>(&red[2 * w]) = rp;
        __syncthreads();
        if (tid < 8) {
            int gg = tid & 3, hi = tid >> 2;            // hi: 0 -> sample g, 1 -> sample g+4
            float a = red[4 * gg + hi];                 // warp 2g partial
            float b = red[4 * gg + 2 + hi];             // warp 2g+1 partial
            out[grp * 8 + gg + 4 * hi] = a + b;
        }
    }
}

// ---------------------------------------------------------------------------
extern "C" void kernel_launch(void* const* d_in, const int* in_sizes, int n_in,
                              void* d_out, int out_size)
{
    const float* x   = (const float*)d_in[0];
    const float* w1  = (const float*)d_in[1];
    const float* b1  = (const float*)d_in[2];
    const float* w2  = (const float*)d_in[3];
    const float* b2  = (const float*)d_in[4];
    const float* fw1 = (const float*)d_in[5];
    const float* fb1 = (const float*)d_in[6];
    const float* fw2 = (const float*)d_in[7];
    const float* fb2 = (const float*)d_in[8];
    const float* fw3 = (const float*)d_in[9];
    const float* fb3 = (const float*)d_in[10];
    const float* dw1 = (const float*)d_in[11];
    const float* db1 = (const float*)d_in[12];
    const float* dw2 = (const float*)d_in[13];
    const float* db2 = (const float*)d_in[14];

    const int B = in_sizes[0] / 1024;  // x is [B,1,16,8,8] = B*1024 floats
    const size_t smem = SM_FLOATS * sizeof(float);

    prep_kernel<<<64, 64>>>(fw1, fb1, fw2, fb2, fw3, fb3, dw1, db1, dw2, db2);

    cudaFuncSetAttribute(main_kernel, cudaFuncAttributeMaxDynamicSharedMemorySize, (int)smem);
    main_kernel<<<148, THREADS, smem>>>(x, w1, b1, w2, b2, (float*)d_out, B);
}